// round 4
// baseline (speedup 1.0000x reference)
#include <cuda_runtime.h>

// N = 4096, B = 8192 (from reference). Diag cache: 4096 floats = 16 KB.
#define DIAG_N 4096
#define BATCH_B 8192

__device__ float4 g_diag4[DIAG_N / 4];

// Gather the diagonal of the 4096x4096 kernel matrix into a compact array.
// Strided reads (stride N+1 floats) touch 4096 distinct 128B lines once.
__global__ void diag_gather_kernel(const float* __restrict__ kmat) {
    int i = blockIdx.x * blockDim.x + threadIdx.x;
    if (i < DIAG_N) {
        reinterpret_cast<float*>(g_diag4)[i] =
            kmat[(size_t)i * (DIAG_N + 1)];
    }
}

// Pure streaming column-scale: out[b,n] = x[b,n] * diag[n].
// One float4 per thread; diag indexed by (global float4 idx) & (N/4 - 1),
// which is L2-resident (16 KB) and coalesced within each warp.
__global__ void diag_scale_kernel(const float4* __restrict__ x,
                                  float4* __restrict__ out) {
    size_t g = (size_t)blockIdx.x * blockDim.x + threadIdx.x;
    float4 v = x[g];
    float4 d = g_diag4[g & (DIAG_N / 4 - 1)];
    v.x *= d.x;
    v.y *= d.y;
    v.z *= d.z;
    v.w *= d.w;
    out[g] = v;
}

extern "C" void kernel_launch(void* const* d_in, const int* in_sizes, int n_in,
                              void* d_out, int out_size) {
    const float* x    = (const float*)d_in[0];   // [B, N] fp32
    const float* kmat = (const float*)d_in[1];   // [N, N] fp32
    float* out        = (float*)d_out;           // [B, N] fp32

    // 1. Gather diagonal (16 KB) into device-global cache.
    diag_gather_kernel<<<(DIAG_N + 255) / 256, 256>>>(kmat);

    // 2. Streaming scale: B*N/4 float4 elements, exact grid.
    const size_t total4 = (size_t)BATCH_B * DIAG_N / 4;  // 8,388,608
    const int threads = 256;
    const int blocks = (int)(total4 / threads);          // 32768, exact
    diag_scale_kernel<<<blocks, threads>>>(
        (const float4*)x, (float4*)out);
}